// round 17
// baseline (speedup 1.0000x reference)
#include <cuda_runtime.h>
#include <math.h>
#include <stdint.h>

#define B_   64
#define T_   1024
#define C_   192
#define BT_  (B_*T_)
#define NPROJ 29
#define PGRID 152
#define NCHUNK64 (BT_/64)    // 1024 (gemm kernel)
#define NCHUNK32 (BT_/32)    // 2048 (layer kernel)

#define ASTRIDE 200          // == 8 mod 32 -> conflict-free LDS.64
#define WSTRIDE 200
#define ABUF    (32*ASTRIDE)      // one 32-row A buffer (words)
#define A_ELEMS (64*ASTRIDE)      // = 2*ABUF  (gemm kernel A / layer double-buffer)
#define W_ELEMS (192*WSTRIDE)
#define RED_OFF (A_ELEMS + W_ELEMS)
#define SMEM_MMA ((RED_OFF + 1024) * 4)   // 208896 B

// ---------------- scratch ----------------
__device__ float g_xc  [(size_t)BT_*C_];
__device__ float g_act [(size_t)BT_*C_];
__device__ float g_tmp [(size_t)BT_*C_];
__device__ float g_cond[B_*C_];
__device__ float g_z0[BT_];
__device__ float g_z1[BT_];
__device__ float g_hp[(size_t)BT_*NPROJ];

__device__ __forceinline__ float gelu_exact(float x){
    return 0.5f*x*(1.0f + erff(x*0.70710678118654752f));
}
__device__ __forceinline__ uint32_t to_tf32(float f){
    uint32_t r; asm("cvt.rna.tf32.f32 %0, %1;" : "=r"(r) : "f"(f)); return r;
}
// within each 8-k group store order [0,4,1,5,2,6,3,7] so (q, q+4) is one LDS.64
__device__ __forceinline__ int kperm(int k){
    int o = k & 7;
    return (k & ~7) + ((o < 4) ? (o*2) : ((o-4)*2 + 1));
}
__device__ __forceinline__ void mma1688(float* d, const uint32_t* a, const uint32_t* b){
    asm volatile("mma.sync.aligned.m16n8k8.row.col.f32.tf32.tf32.f32 "
                 "{%0,%1,%2,%3}, {%4,%5,%6,%7}, {%8,%9}, {%0,%1,%2,%3};"
                 : "+f"(d[0]), "+f"(d[1]), "+f"(d[2]), "+f"(d[3])
                 : "r"(a[0]), "r"(a[1]), "r"(a[2]), "r"(a[3]),
                   "r"(b[0]), "r"(b[1]));
}

__device__ __forceinline__ void stage_W(const float* __restrict__ pww, uint32_t* Wsm, int tid){
#pragma unroll
    for (int j = 0; j < 18; j++){
        int i = tid + j*512;
        int n = i / 48, kq = i % 48;
        float4 v = *(const float4*)(pww + (size_t)n*C_ + kq*4);
        uint32_t* p = Wsm + n*WSTRIDE;
        p[kperm(kq*4+0)] = to_tf32(v.x);
        p[kperm(kq*4+1)] = to_tf32(v.y);
        p[kperm(kq*4+2)] = to_tf32(v.z);
        p[kperm(kq*4+3)] = to_tf32(v.w);
    }
}

// ================= persistent fused DDS layer: producer/consumer specialization =================
// warps 8-15 produce A (dwconv+LN1+GELU) for chunk n+stride; warps 0-7 consume chunk n
// (MMA over K=192 + LN2 + GELU + residual + store). 32-row chunks, double-buffered A.
// hh_mode: effective input = prew[c]*x0[bt] + preb[c] + xin[bt,c]
__global__ void __launch_bounds__(512,1) k_layer_mma(
    const float* __restrict__ xin, float* __restrict__ xout,
    const float* __restrict__ dww, const float* __restrict__ dwb,
    const float* __restrict__ n1g, const float* __restrict__ n1b,
    const float* __restrict__ pww, const float* __restrict__ pwb,
    const float* __restrict__ n2g, const float* __restrict__ n2b,
    const float* __restrict__ mask, int dil, int apply_mask,
    const float* __restrict__ x0g, const float* __restrict__ prew,
    const float* __restrict__ preb, int hh_mode)
{
    extern __shared__ uint32_t sm[];
    uint32_t* Ab0 = sm;
    uint32_t* Ab1 = sm + ABUF;
    uint32_t* Wsm = sm + A_ELEMS;
    float* red1 = (float*)(sm + RED_OFF);      // [8][32]
    float* red2 = red1 + 256;
    const int tid = threadIdx.x;
    const int w = tid >> 5, lane = tid & 31;
    const int r = lane >> 2, q = lane & 3;
    const bool prod = (w >= 8);

    stage_W(pww, Wsm, tid);

    // interleaved column base for prologue stores: c = lane + 32j
    const int lo = lane & 7;
    const int cpos0 = (lane & ~7) + ((lo < 4) ? lo*2 : (lo-4)*2 + 1);

    // role-specific cached params
    float c_n1g[6], c_n1b[6], c_dw0[6], c_dw1[6], c_dw2[6], c_dwb[6];          // producers
    float bias0[3], bias1[3], e_g0[3], e_g1[3], e_b0[3], e_b1[3];              // consumers
    if (prod){
#pragma unroll
        for (int j = 0; j < 6; j++){
            int c = lane + 32*j;
            c_n1g[j] = n1g[c]; c_n1b[j] = n1b[c];
            c_dw0[j] = dww[c*3+0]; c_dw1[j] = dww[c*3+1]; c_dw2[j] = dww[c*3+2];
            c_dwb[j] = dwb[c];
        }
    } else {
#pragma unroll
        for (int n = 0; n < 3; n++){
            int col = w*24 + n*8 + q*2;
            bias0[n] = pwb[col]; bias1[n] = pwb[col+1];
            e_g0[n] = n2g[col]; e_g1[n] = n2g[col+1];
            e_b0[n] = n2b[col]; e_b1[n] = n2b[col+1];
        }
    }

    // ---- producer body as a statement macro (32 rows into Adst) ----
#define PRODUCE(cchunk, Adst) do{                                               \
        const int bt0p = (cchunk) * 32;                                         \
        const int bp = bt0p >> 10, t0p = bt0p & 1023;                           \
        const float* mbp = mask + bp*T_;                                        \
        const float* xbp = xin + (size_t)bp*T_*C_;                              \
        const float* x0bp = hh_mode ? (x0g + bp*T_) : (const float*)0;          \
        int pw = w - 8;                                                         \
        _Pragma("unroll 1")                                                     \
        for (int i = 0; i < 4; i++){                                            \
            int rr = i*8 + pw;                                                  \
            int t = t0p + rr;                                                   \
            int tm = t - dil, tp = t + dil;                                     \
            float mm = mbp[t];                                                  \
            float ml = (tm >= 0) ? mbp[tm] : 0.f;                               \
            float mr = (tp < T_) ? mbp[tp] : 0.f;                               \
            int tmc = (tm >= 0) ? tm : 0;                                       \
            int tpc = (tp < T_) ? tp : (T_-1);                                  \
            const float* xm_ = xbp + (size_t)t*C_;                              \
            const float* xl_ = xbp + (size_t)tmc*C_;                            \
            const float* xr_ = xbp + (size_t)tpc*C_;                            \
            float x0m = 0.f, x0l = 0.f, x0r = 0.f;                              \
            if (hh_mode){ x0m = x0bp[t]; x0l = x0bp[tmc]; x0r = x0bp[tpc]; }    \
            float y[6]; float s1 = 0.f, s2 = 0.f;                               \
            _Pragma("unroll")                                                   \
            for (int j = 0; j < 6; j++){                                        \
                int c = lane + 32*j;                                            \
                float vl = xl_[c], vm = xm_[c], vr = xr_[c];                    \
                if (hh_mode){                                                   \
                    float pwv = prew[c], pbv = preb[c];                         \
                    vl = fmaf(pwv, x0l, pbv) + vl;                              \
                    vm = fmaf(pwv, x0m, pbv) + vm;                              \
                    vr = fmaf(pwv, x0r, pbv) + vr;                              \
                }                                                               \
                float v = fmaf(c_dw0[j], vl*ml,                                 \
                          fmaf(c_dw1[j], vm*mm,                                 \
                          fmaf(c_dw2[j], vr*mr, c_dwb[j])));                    \
                y[j] = v; s1 += v; s2 += v*v;                                   \
            }                                                                   \
            _Pragma("unroll")                                                   \
            for (int o = 16; o > 0; o >>= 1){                                   \
                s1 += __shfl_xor_sync(0xffffffffu, s1, o);                      \
                s2 += __shfl_xor_sync(0xffffffffu, s2, o);                      \
            }                                                                   \
            float mean = s1*(1.f/192.f);                                        \
            float var  = s2*(1.f/192.f) - mean*mean;                            \
            float rstd = rsqrtf(var + 1e-5f);                                   \
            _Pragma("unroll")                                                   \
            for (int j = 0; j < 6; j++){                                        \
                float yn = c_n1g[j]*(y[j] - mean)*rstd + c_n1b[j];              \
                (Adst)[rr*ASTRIDE + cpos0 + 32*j] = to_tf32(gelu_exact(yn));    \
            }                                                                   \
        }                                                                       \
    } while(0)

    // pipeline preload: producers fill Ab0 with this CTA's first chunk
    if (prod) PRODUCE(blockIdx.x, Ab0);
    __syncthreads();

    int s = 0;
    for (int c0 = blockIdx.x; c0 < NCHUNK32; c0 += gridDim.x){
        uint32_t* Acur = s ? Ab1 : Ab0;
        uint32_t* Anxt = s ? Ab0 : Ab1;
        if (prod){
            int cn = c0 + gridDim.x;
            if (cn < NCHUNK32) PRODUCE(cn, Anxt);
        } else {
            const int bt0 = c0 * 32;
            // ---- MMA over K=192 (M32 rows, this warp: cols w*24..w*24+23) ----
            float acc[2][3][4];
#pragma unroll
            for (int t = 0; t < 2; t++)
#pragma unroll
                for (int n = 0; n < 3; n++)
#pragma unroll
                    for (int k = 0; k < 4; k++) acc[t][n][k] = 0.f;
            {
                const uint32_t* ab = Acur + r*ASTRIDE + 2*q;
                const uint32_t* wb = Wsm + (w*24 + r)*WSTRIDE + 2*q;
#pragma unroll 4
                for (int kc = 0; kc < C_; kc += 8){
                    uint2 a00 = *(const uint2*)(ab + kc);
                    uint2 a08 = *(const uint2*)(ab + 8*ASTRIDE + kc);
                    uint2 a10 = *(const uint2*)(ab + 16*ASTRIDE + kc);
                    uint2 a18 = *(const uint2*)(ab + 24*ASTRIDE + kc);
                    uint2 bv0 = *(const uint2*)(wb + kc);
                    uint2 bv1 = *(const uint2*)(wb + 8*WSTRIDE + kc);
                    uint2 bv2 = *(const uint2*)(wb + 16*WSTRIDE + kc);
                    uint32_t a0[4] = {a00.x, a08.x, a00.y, a08.y};
                    uint32_t a1[4] = {a10.x, a18.x, a10.y, a18.y};
                    uint32_t b0[2] = {bv0.x, bv0.y};
                    uint32_t b1[2] = {bv1.x, bv1.y};
                    uint32_t b2[2] = {bv2.x, bv2.y};
                    mma1688(acc[0][0], a0, b0);
                    mma1688(acc[0][1], a0, b1);
                    mma1688(acc[0][2], a0, b2);
                    mma1688(acc[1][0], a1, b0);
                    mma1688(acc[1][1], a1, b1);
                    mma1688(acc[1][2], a1, b2);
                }
            }
            // ---- per-row partial sums for LN2 ----
            float s1a[2][2] = {{0,0},{0,0}}, s2a[2][2] = {{0,0},{0,0}};
#pragma unroll
            for (int t = 0; t < 2; t++)
#pragma unroll
                for (int n = 0; n < 3; n++){
                    float v0 = acc[t][n][0] + bias0[n];
                    float v1 = acc[t][n][1] + bias1[n];
                    float v2 = acc[t][n][2] + bias0[n];
                    float v3 = acc[t][n][3] + bias1[n];
                    s1a[t][0] += v0 + v1; s2a[t][0] += v0*v0 + v1*v1;
                    s1a[t][1] += v2 + v3; s2a[t][1] += v2*v2 + v3*v3;
                }
#pragma unroll
            for (int t = 0; t < 2; t++)
#pragma unroll
                for (int h = 0; h < 2; h++){
#pragma unroll
                    for (int o = 1; o < 4; o <<= 1){
                        s1a[t][h] += __shfl_xor_sync(0xffffffffu, s1a[t][h], o);
                        s2a[t][h] += __shfl_xor_sync(0xffffffffu, s2a[t][h], o);
                    }
                }
            if (q == 0){
#pragma unroll
                for (int t = 0; t < 2; t++)
#pragma unroll
                    for (int h = 0; h < 2; h++){
                        int row = t*16 + h*8 + r;
                        red1[w*32 + row] = s1a[t][h];
                        red2[w*32 + row] = s2a[t][h];
                    }
            }
            asm volatile("bar.sync 1, 256;" ::: "memory");   // consumers only
            // ---- epilogue ----
#pragma unroll
            for (int t = 0; t < 2; t++)
#pragma unroll
                for (int h = 0; h < 2; h++){
                    int row = t*16 + h*8 + r;
                    float tot1 = 0.f, tot2 = 0.f;
#pragma unroll
                    for (int k = 0; k < 8; k++){ tot1 += red1[k*32+row]; tot2 += red2[k*32+row]; }
                    float mean = tot1*(1.f/192.f);
                    float var  = tot2*(1.f/192.f) - mean*mean;
                    float rstd = rsqrtf(var + 1e-5f);
                    int grow = bt0 + row;
                    float m = apply_mask ? mask[grow] : 1.f;
                    float x0v = hh_mode ? x0g[grow] : 0.f;
                    const float* resp = xin + (size_t)grow*C_;
                    float* outp = xout + (size_t)grow*C_;
#pragma unroll
                    for (int n = 0; n < 3; n++){
                        int col = w*24 + n*8 + q*2;
                        float v0 = acc[t][n][h*2+0] + bias0[n];
                        float v1 = acc[t][n][h*2+1] + bias1[n];
                        float2 res = *(const float2*)(resp + col);
                        float rx = res.x, ry = res.y;
                        if (hh_mode){
                            rx = fmaf(prew[col+0], x0v, preb[col+0]) + rx;
                            ry = fmaf(prew[col+1], x0v, preb[col+1]) + ry;
                        }
                        float2 o2;
                        o2.x = rx + gelu_exact(e_g0[n]*(v0-mean)*rstd + e_b0[n]);
                        o2.y = ry + gelu_exact(e_g1[n]*(v1-mean)*rstd + e_b1[n]);
                        if (apply_mask){ o2.x *= m; o2.y *= m; }
                        *(float2*)(outp + col) = o2;
                    }
                }
        }
        __syncthreads();
        s ^= 1;
    }
#undef PRODUCE
}

// ---------------- persistent plain tf32 MMA GEMM (64-row chunks, 16 warps) ----------------
// xbct != null: A rows come from x in (B,C,T) layout (fused transpose)
__global__ void __launch_bounds__(512,1) k_gemm_mma(
    const float* __restrict__ xin, float* __restrict__ xout,
    const float* __restrict__ pww, const float* __restrict__ pwb,
    const float* __restrict__ cond, const float* __restrict__ mask,
    const float* __restrict__ xbct)
{
    extern __shared__ uint32_t sm[];
    uint32_t* Asm = sm;
    uint32_t* Wsm = sm + A_ELEMS;
    const int tid = threadIdx.x;
    const int w = tid >> 5, lane = tid & 31;
    const int wm = w >> 3, wn = w & 7;
    const int r = lane >> 2, q = lane & 3;

    stage_W(pww, Wsm, tid);

    float pb0[3], pb1[3];
#pragma unroll
    for (int n = 0; n < 3; n++){
        int col = wn*24 + n*8 + q*2;
        pb0[n] = pwb[col]; pb1[n] = pwb[col+1];
    }

    for (int c0 = blockIdx.x; c0 < NCHUNK64; c0 += gridDim.x){
        const int rb = c0 * 64;
        const int b = rb >> 10;
        if (xbct){
            const float* xb = xbct + (size_t)b*C_*T_;
            const int t0 = rb & 1023;
            for (int cc = w; cc < C_; cc += 16){
                float v0 = xb[(size_t)cc*T_ + t0 + lane];
                float v1 = xb[(size_t)cc*T_ + t0 + 32 + lane];
                int kp = kperm(cc);
                Asm[lane*ASTRIDE + kp]      = to_tf32(v0);
                Asm[(lane+32)*ASTRIDE + kp] = to_tf32(v1);
            }
        } else {
#pragma unroll
            for (int j = 0; j < 6; j++){
                int i = tid + j*512;
                int r2 = i / 48, kq = i % 48;
                float4 v = *(const float4*)(xin + (size_t)(rb + r2)*C_ + kq*4);
                uint32_t* p = Asm + r2*ASTRIDE;
                p[kperm(kq*4+0)] = to_tf32(v.x);
                p[kperm(kq*4+1)] = to_tf32(v.y);
                p[kperm(kq*4+2)] = to_tf32(v.z);
                p[kperm(kq*4+3)] = to_tf32(v.w);
            }
        }
        __syncthreads();

        float acc[2][3][4];
#pragma unroll
        for (int t = 0; t < 2; t++)
#pragma unroll
            for (int n = 0; n < 3; n++)
#pragma unroll
                for (int k = 0; k < 4; k++) acc[t][n][k] = 0.f;
        {
            const uint32_t* ab = Asm + (wm*32 + r)*ASTRIDE + 2*q;
            const uint32_t* wb = Wsm + (wn*24 + r)*WSTRIDE + 2*q;
#pragma unroll 4
            for (int kc = 0; kc < C_; kc += 8){
                uint2 a00 = *(const uint2*)(ab + kc);
                uint2 a08 = *(const uint2*)(ab + 8*ASTRIDE + kc);
                uint2 a10 = *(const uint2*)(ab + 16*ASTRIDE + kc);
                uint2 a18 = *(const uint2*)(ab + 24*ASTRIDE + kc);
                uint2 bv0 = *(const uint2*)(wb + kc);
                uint2 bv1 = *(const uint2*)(wb + 8*WSTRIDE + kc);
                uint2 bv2 = *(const uint2*)(wb + 16*WSTRIDE + kc);
                uint32_t a0[4] = {a00.x, a08.x, a00.y, a08.y};
                uint32_t a1[4] = {a10.x, a18.x, a10.y, a18.y};
                uint32_t b0[2] = {bv0.x, bv0.y};
                uint32_t b1[2] = {bv1.x, bv1.y};
                uint32_t b2[2] = {bv2.x, bv2.y};
                mma1688(acc[0][0], a0, b0);
                mma1688(acc[0][1], a0, b1);
                mma1688(acc[0][2], a0, b2);
                mma1688(acc[1][0], a1, b0);
                mma1688(acc[1][1], a1, b1);
                mma1688(acc[1][2], a1, b2);
            }
        }
        __syncthreads();                      // A consumed; safe for next prologue

        float bias0[3], bias1[3];
#pragma unroll
        for (int n = 0; n < 3; n++){
            bias0[n] = pb0[n]; bias1[n] = pb1[n];
            if (cond){
                int col = wn*24 + n*8 + q*2;
                bias0[n] += cond[b*C_ + col]; bias1[n] += cond[b*C_ + col+1];
            }
        }
#pragma unroll
        for (int t = 0; t < 2; t++)
#pragma unroll
            for (int h = 0; h < 2; h++){
                int row = wm*32 + t*16 + h*8 + r;
                int grow = rb + row;
                float m = mask ? mask[grow] : 1.f;
                float* outp = xout + (size_t)grow*C_;
#pragma unroll
                for (int n = 0; n < 3; n++){
                    int col = wn*24 + n*8 + q*2;
                    float2 o2;
                    o2.x = (acc[t][n][h*2+0] + bias0[n]) * m;
                    o2.y = (acc[t][n][h*2+1] + bias1[n]) * m;
                    *(float2*)(outp + col) = o2;
                }
            }
    }
}

// ---------------- cond[b,o] ----------------
__global__ void k_cond(const float* __restrict__ embed, const float* __restrict__ cw,
                       const float* __restrict__ cb, float* __restrict__ cond){
    int b = blockIdx.x, o = threadIdx.x;
    __shared__ float se[C_];
    se[o] = embed[b*C_ + o];
    __syncthreads();
    float s = cb[o];
    const float* wr = cw + (size_t)o*C_;
#pragma unroll 8
    for (int c = 0; c < C_; c++) s = fmaf(se[c], wr[c], s);
    cond[b*C_ + o] = s;
}

// ---------------- noise -> z0/z1 ----------------
__global__ void k_noise(const float* __restrict__ noise, float* __restrict__ z0, float* __restrict__ z1){
    int idx = blockIdx.x*256 + threadIdx.x;
    int b = idx >> 10, t = idx & 1023;
    z0[idx] = noise[(size_t)b*2*T_ + t];
    z1[idx] = noise[(size_t)b*2*T_ + T_ + t];
}

// ---------------- proj 29x192 GEMM ----------------
__global__ void __launch_bounds__(928) k_proj29(
    const float* __restrict__ hh, const float* __restrict__ w,
    const float* __restrict__ bias, const float* __restrict__ mask,
    float* __restrict__ out)
{
    __shared__ float sh[32][193];
    int tid = threadIdx.x;
    size_t base = (size_t)blockIdx.x * 32 * C_;
    for (int i = tid; i < 32*C_; i += 928)
        sh[i/C_][i%C_] = hh[base + i];
    __syncthreads();
    int tl = tid & 31, p = tid >> 5;
    if (p < NPROJ){
        float s = bias[p];
        const float* wp = w + (size_t)p*C_;
#pragma unroll 8
        for (int c = 0; c < C_; c++) s = fmaf(sh[tl][c], wp[c], s);
        int bt = blockIdx.x*32 + tl;
        out[(size_t)bt*NPROJ + p] = s * mask[bt];
    }
}

// ---------------- rational-quadratic spline inverse (+ optional final affine) ----------------
__global__ void k_rqs(const float* __restrict__ hp, float* __restrict__ z1,
                      float* __restrict__ z0, const float* __restrict__ mask,
                      int do_final, const float* __restrict__ ea_m,
                      const float* __restrict__ ea_logs, float* __restrict__ outg)
{
    int bt = blockIdx.x*256 + threadIdx.x;
    const float* h = hp + (size_t)bt*NPROJ;
    const float sc = 0.07216878364870323f;

    float w[10], cw[11];
    {
        float u[10]; float mx = -1e30f;
#pragma unroll
        for (int j = 0; j < 10; j++){ u[j] = h[j]*sc; mx = fmaxf(mx, u[j]); }
        float s = 0.f;
#pragma unroll
        for (int j = 0; j < 10; j++){ u[j] = expf(u[j]-mx); s += u[j]; }
        float inv = 1.0f/s, accum = 0.f;
        cw[0] = -5.0f;
#pragma unroll
        for (int j = 0; j < 10; j++){
            float wj = 0.001f + 0.99f*u[j]*inv;
            accum += wj;
            cw[j+1] = 10.0f*accum - 5.0f;
        }
        cw[10] = 5.0f;
#pragma unroll
        for (int j = 0; j < 10; j++) w[j] = cw[j+1]-cw[j];
    }
    float hb[10], ch[11];
    {
        float u[10]; float mx = -1e30f;
#pragma unroll
        for (int j = 0; j < 10; j++){ u[j] = h[10+j]*sc; mx = fmaxf(mx, u[j]); }
        float s = 0.f;
#pragma unroll
        for (int j = 0; j < 10; j++){ u[j] = expf(u[j]-mx); s += u[j]; }
        float inv = 1.0f/s, accum = 0.f;
        ch[0] = -5.0f;
#pragma unroll
        for (int j = 0; j < 10; j++){
            float hj = 0.001f + 0.99f*u[j]*inv;
            accum += hj;
            ch[j+1] = 10.0f*accum - 5.0f;
        }
        ch[10] = 5.0f;
#pragma unroll
        for (int j = 0; j < 10; j++) hb[j] = ch[j+1]-ch[j];
    }
    float d[11];
    {
        const float ucst = 0.5413248546129181f;
        float v = log1pf(expf(ucst));
        d[0] = 0.001f + v; d[10] = d[0];
#pragma unroll
        for (int j = 1; j <= 9; j++){
            float u = h[19 + j];
            float spv = (u > 20.f) ? u : log1pf(expf(u));
            d[j] = 0.001f + spv;
        }
    }
    float xin = z1[bt];
    float xcl = fminf(fmaxf(xin, -5.f), 5.f);
    int idx = 0;
#pragma unroll
    for (int j = 0; j < 11; j++){
        float loc = ch[j] + ((j == 10) ? 1e-6f : 0.f);
        idx += (xcl >= loc) ? 1 : 0;
    }
    idx = min(max(idx - 1, 0), 9);
    float bw = w[idx], bcw = cw[idx], bh = hb[idx], bch = ch[idx];
    float d0 = d[idx], d1 = d[idx+1];
    float delta = bh / bw;
    float two = d0 + d1 - 2.f*delta;
    float y = xcl - bch;
    float a  = y*two + bh*(delta - d0);
    float bbq = bh*d0 - y*two;
    float c  = -delta*y;
    float disc = fmaxf(bbq*bbq - 4.f*a*c, 0.f);
    float root = 2.f*c / (-bbq - sqrtf(disc));
    float outv = root*bw + bcw;
    bool inside = (xin >= -5.f) && (xin <= 5.f);
    float res = inside ? outv : xin;
    float m = mask[bt];
    if (do_final){
        outg[bt] = (res*m - ea_m[0]) * expf(-ea_logs[0]) * m;
    } else {
        z1[bt] = res * m;
        z0[bt] = z0[bt] * m;
    }
}

// ================= host =================
extern "C" void kernel_launch(void* const* d_in, const int* in_sizes, int n_in,
                              void* d_out, int out_size)
{
    const float* x        = (const float*)d_in[0];
    const float* mask     = (const float*)d_in[1];
    const float* embed    = (const float*)d_in[2];
    const float* noise    = (const float*)d_in[3];
    const float* pre_w    = (const float*)d_in[4];
    const float* pre_b    = (const float*)d_in[5];
    const float* cond_w   = (const float*)d_in[6];
    const float* cond_b   = (const float*)d_in[7];
    const float* dds_dw_w = (const float*)d_in[8];
    const float* dds_dw_b = (const float*)d_in[9];
    const float* dds_pw_w = (const float*)d_in[10];
    const float* dds_pw_b = (const float*)d_in[11];
    const float* dds_n1_g = (const float*)d_in[12];
    const float* dds_n1_b = (const float*)d_in[13];
    const float* dds_n2_g = (const float*)d_in[14];
    const float* dds_n2_b = (const float*)d_in[15];
    const float* proj_w   = (const float*)d_in[16];
    const float* proj_b   = (const float*)d_in[17];
    const float* ea_m     = (const float*)d_in[18];
    const float* ea_logs  = (const float*)d_in[19];
    const float* cf_pre_w = (const float*)d_in[20];
    const float* cf_pre_b = (const float*)d_in[21];
    const float* cf_dw_w  = (const float*)d_in[22];
    const float* cf_dw_b  = (const float*)d_in[23];
    const float* cf_pw_w  = (const float*)d_in[24];
    const float* cf_pw_b  = (const float*)d_in[25];
    const float* cf_n1_g  = (const float*)d_in[26];
    const float* cf_n1_b  = (const float*)d_in[27];
    const float* cf_n2_g  = (const float*)d_in[28];
    const float* cf_n2_b  = (const float*)d_in[29];
    const float* cf_projw = (const float*)d_in[30];
    const float* cf_projb = (const float*)d_in[31];
    float* out = (float*)d_out;

    float *xc, *act, *tmp, *cond, *z0, *z1, *hp;
    cudaGetSymbolAddress((void**)&xc,   g_xc);
    cudaGetSymbolAddress((void**)&act,  g_act);
    cudaGetSymbolAddress((void**)&tmp,  g_tmp);
    cudaGetSymbolAddress((void**)&cond, g_cond);
    cudaGetSymbolAddress((void**)&z0,   g_z0);
    cudaGetSymbolAddress((void**)&z1,   g_z1);
    cudaGetSymbolAddress((void**)&hp,   g_hp);

    cudaFuncSetAttribute(k_layer_mma, cudaFuncAttributeMaxDynamicSharedMemorySize, SMEM_MMA);
    cudaFuncSetAttribute(k_gemm_mma,  cudaFuncAttributeMaxDynamicSharedMemorySize, SMEM_MMA);

    const int dils[3] = {1, 3, 9};

    k_cond<<<B_, C_>>>(embed, cond_w, cond_b, cond);
    // pre conv1x1 with fused transpose from (B,C,T)
    k_gemm_mma<<<PGRID, 512, SMEM_MMA>>>(nullptr, act, pre_w, pre_b, cond, nullptr, x);
    {
        float* bin = act; float* bout = tmp;
        for (int l = 0; l < 3; l++){
            k_layer_mma<<<PGRID, 512, SMEM_MMA>>>(bin, bout,
                dds_dw_w + (size_t)l*C_*3, dds_dw_b + (size_t)l*C_,
                dds_n1_g + (size_t)l*C_, dds_n1_b + (size_t)l*C_,
                dds_pw_w + (size_t)l*C_*C_, dds_pw_b + (size_t)l*C_,
                dds_n2_g + (size_t)l*C_, dds_n2_b + (size_t)l*C_,
                mask, dils[l], (l == 2) ? 1 : 0,
                nullptr, nullptr, nullptr, 0);
            float* t_ = bin; bin = bout; bout = t_;
        }
        k_gemm_mma<<<PGRID, 512, SMEM_MMA>>>(bin, xc, proj_w, proj_b, nullptr, mask, nullptr);
    }

    k_noise<<<BT_/256, 256>>>(noise, z0, z1);

    float* cur0 = z0; float* cur1 = z1;
    const int forder[3] = {3, 2, 1};
    for (int fi = 0; fi < 3; fi++){
        int f = forder[fi];
        float* tp_ = cur0; cur0 = cur1; cur1 = tp_;
        // layer 0 with fused hh: in = xc (+ pre(x0)), out = act
        {
            size_t o1 = ((size_t)f*3 + 0)*C_;
            k_layer_mma<<<PGRID, 512, SMEM_MMA>>>(xc, act,
                cf_dw_w + o1*3, cf_dw_b + o1,
                cf_n1_g + o1, cf_n1_b + o1,
                cf_pw_w + o1*C_, cf_pw_b + o1,
                cf_n2_g + o1, cf_n2_b + o1,
                mask, dils[0], 0,
                cur0, cf_pre_w + (size_t)f*C_, cf_pre_b + (size_t)f*C_, 1);
        }
        // layers 1,2
        float* bin = act; float* bout = tmp;
        for (int l = 1; l < 3; l++){
            size_t o1 = ((size_t)f*3 + l)*C_;
            k_layer_mma<<<PGRID, 512, SMEM_MMA>>>(bin, bout,
                cf_dw_w + o1*3, cf_dw_b + o1,
                cf_n1_g + o1, cf_n1_b + o1,
                cf_pw_w + o1*C_, cf_pw_b + o1,
                cf_n2_g + o1, cf_n2_b + o1,
                mask, dils[l], (l == 2) ? 1 : 0,
                nullptr, nullptr, nullptr, 0);
            float* t_ = bin; bin = bout; bout = t_;
        }
        // result in act (L0: xc->act, L1: act->tmp, L2: tmp->act)
        k_proj29<<<BT_/32, 928>>>(act, cf_projw + (size_t)f*NPROJ*C_, cf_projb + (size_t)f*NPROJ, mask, hp);
        int last = (fi == 2);
        k_rqs<<<BT_/256, 256>>>(hp, cur1, cur0, mask, last, ea_m, ea_logs, out);
    }
}